// round 15
// baseline (speedup 1.0000x reference)
#include <cuda_runtime.h>
#include <cuda_bf16.h>
#include <math.h>
#include <stdint.h>

#define N_NODES 50000
#define DIM     200
#define K_PAD   224
#define N_RELS  500
#define NHID    100
#define NHEADS  2
#define E_BASE  150000
#define E_NHOP  30000
#define E_ALL   180000

typedef __nv_bfloat16 bf16;

// ---------------- scratch (static device globals; no allocs) ----------------
__device__ __align__(16) bf16 g_xh[N_NODES * K_PAD];
__device__ __align__(16) bf16 g_xl[N_NODES * K_PAD];
__device__ __align__(16) bf16 g_x1h[N_NODES * K_PAD];
__device__ __align__(16) bf16 g_x1l[N_NODES * K_PAD];
// BcatA row order: 0-199 SRC (h0,h1), 200-399 DST (h0,h1), 400-599 W_ent^T
__device__ __align__(16) bf16 g_BAh[600 * K_PAD];
__device__ __align__(16) bf16 g_BAl[600 * K_PAD];
// B2 row order: 0-199 SRC, 200-399 DST
__device__ __align__(16) bf16 g_B2h[400 * K_PAD];
__device__ __align__(16) bf16 g_B2l[400 * K_PAD];
__device__ __align__(16) float g_pd1[N_NODES * 200];
__device__ __align__(16) float g_ps1[N_NODES * 200];
__device__ __align__(16) float g_lin[N_NODES * 200];
__device__ __align__(16) float g_pd2[N_NODES * 200];
__device__ __align__(16) float g_ps2[N_NODES * 200];
__device__ __align__(16) float g_rp1[N_RELS * 200];
__device__ __align__(16) float g_relproj2[N_RELS * DIM];
__device__ int   g_dst[E_ALL];
__device__ int   g_src[E_ALL];
__device__ int   g_rA[E_ALL];
__device__ int   g_rB[E_ALL];
__device__ float g_rowsum1[NHEADS * N_NODES];
__device__ __align__(16) float g_acc1[N_NODES * 200];
__device__ float g_outrel[N_RELS * DIM];
__device__ float g_rowsum2[N_NODES];
__device__ __align__(16) float g_acc2[N_NODES * DIM];
__device__ float g_mask[N_NODES];
__device__ float g_w1[NHEADS * 600];
__device__ float g_w2[600];
__device__ float g_d1[NHEADS * N_NODES];
__device__ float g_s1[NHEADS * N_NODES];
__device__ float g_r1[NHEADS * N_RELS];
__device__ float g_d2[N_NODES];
__device__ float g_s2[N_NODES];
__device__ float g_r2[N_RELS];

// ---------------- helpers ----------------
__device__ __forceinline__ float warp_sum(float v) {
    #pragma unroll
    for (int o = 16; o; o >>= 1) v += __shfl_xor_sync(0xFFFFFFFFu, v, o);
    return v;
}

__device__ __forceinline__ void split_bf16(float x, bf16& hi, bf16& lo) {
    hi = __float2bfloat16_rn(x);
    lo = __float2bfloat16_rn(x - __bfloat162float(hi));
}

__device__ __forceinline__ void red_add_v4(float* addr, float4 v) {
    asm volatile("red.global.add.v4.f32 [%0], {%1,%2,%3,%4};"
                 :: "l"(addr), "f"(v.x), "f"(v.y), "f"(v.z), "f"(v.w) : "memory");
}
__device__ __forceinline__ void red_add_f32(float* addr, float v) {
    asm volatile("red.global.add.f32 [%0], %1;" :: "l"(addr), "f"(v) : "memory");
}

#define LDSM_X4(R, addr) asm volatile( \
    "ldmatrix.sync.aligned.m8n8.x4.shared.b16 {%0,%1,%2,%3}, [%4];" \
    : "=r"((R)[0]), "=r"((R)[1]), "=r"((R)[2]), "=r"((R)[3]) : "r"(addr))
#define MMA_BF16(C, A, B) asm volatile( \
    "mma.sync.aligned.m16n8k16.row.col.f32.bf16.bf16.f32 " \
    "{%0,%1,%2,%3}, {%4,%5,%6,%7}, {%8,%9}, {%0,%1,%2,%3};" \
    : "+f"((C)[0]), "+f"((C)[1]), "+f"((C)[2]), "+f"((C)[3]) \
    : "r"((A)[0]), "r"((A)[1]), "r"((A)[2]), "r"((A)[3]), "r"((B)[0]), "r"((B)[1]))

__device__ __forceinline__ void cp_async16(uint32_t dst, const void* src, int szbytes) {
    asm volatile("cp.async.cg.shared.global [%0], [%1], 16, %2;"
                 :: "r"(dst), "l"(src), "r"(szbytes));
}
#define CP_COMMIT() asm volatile("cp.async.commit_group;")
#define CP_WAIT(N)  asm volatile("cp.async.wait_group %0;" :: "n"(N))

// pack two bf16 into one 32-bit lane value
__device__ __forceinline__ uint32_t pack_bf2(bf16 a, bf16 b) {
    uint16_t ua = *(uint16_t*)&a, ub = *(uint16_t*)&b;
    return (uint32_t)ua | ((uint32_t)ub << 16);
}

// ---------------- l2norm + bf16 split (NO w1 dependency; float4) ----------
__global__ void l2norm_x(const float* __restrict__ in) {
    int n = (blockIdx.x * blockDim.x + threadIdx.x) >> 5;
    int lane = threadIdx.x & 31;
    if (n >= N_NODES) return;
    const float4* r = (const float4*)(in + (size_t)n * DIM);
    float4 v[2];
    float ss = 0.f;
    #pragma unroll
    for (int it = 0; it < 2; it++) {
        int q = lane + 32 * it;
        if (q < 50) {
            float4 x = r[q];
            v[it] = x;
            ss += x.x * x.x + x.y * x.y + x.z * x.z + x.w * x.w;
        } else {
            v[it] = make_float4(0.f, 0.f, 0.f, 0.f);
        }
    }
    ss = warp_sum(ss);
    float sc = 1.f / fmaxf(sqrtf(ss), 1e-12f);
    uint32_t* xh = (uint32_t*)(g_xh + (size_t)n * K_PAD);
    uint32_t* xl = (uint32_t*)(g_xl + (size_t)n * K_PAD);
    #pragma unroll
    for (int it = 0; it < 2; it++) {
        int q = lane + 32 * it;
        if (q < 56) {
            float4 x = v[it];
            x.x *= sc; x.y *= sc; x.z *= sc; x.w *= sc;
            bf16 h0, l0, h1, l1, h2, l2, h3, l3;
            split_bf16(x.x, h0, l0); split_bf16(x.y, h1, l1);
            split_bf16(x.z, h2, l2); split_bf16(x.w, h3, l3);
            xh[q * 2]     = pack_bf2(h0, h1);
            xh[q * 2 + 1] = pack_bf2(h2, h3);
            xl[q * 2]     = pack_bf2(l0, l1);
            xl[q * 2 + 1] = pack_bf2(l2, l3);
        }
    }
}

// ---------------- layer-1 node scalars (side stream; reads split x) -------
__global__ void node_scalars1() {
    int n = (blockIdx.x * blockDim.x + threadIdx.x) >> 5;
    int lane = threadIdx.x & 31;
    if (n >= N_NODES) return;
    const bf16* xh = g_xh + (size_t)n * K_PAD;
    const bf16* xl = g_xl + (size_t)n * K_PAD;
    float a = 0.f, b = 0.f, c = 0.f, d = 0.f;
    #pragma unroll
    for (int t = 0; t < 7; t++) {
        int j = lane + 32 * t;
        if (j < DIM) {
            float xv = __bfloat162float(xh[j]) + __bfloat162float(xl[j]);
            a += xv * g_w1[j];
            b += xv * g_w1[200 + j];
            c += xv * g_w1[600 + j];
            d += xv * g_w1[800 + j];
        }
    }
    a = warp_sum(a); b = warp_sum(b); c = warp_sum(c); d = warp_sum(d);
    if (lane == 0) {
        g_d1[n] = a; g_s1[n] = b;
        g_d1[N_NODES + n] = c; g_s1[N_NODES + n] = d;
    }
}

// ---------------- folded attention vectors (warp per output) ----------------
__global__ void fold_w(const float* __restrict__ a_heads, const float* __restrict__ a2_h,
                       const float* __restrict__ a_out,   const float* __restrict__ a2_o) {
    int wid = (blockIdx.x * blockDim.x + threadIdx.x) >> 5;
    int lane = threadIdx.x & 31;
    if (wid < NHEADS * 600) {
        int h = wid / 600, k = wid % 600;
        float s = 0.f;
        for (int j = lane; j < NHID; j += 32)
            s += a_heads[(h * NHID + j) * 600 + k] * a2_h[h * NHID + j];
        s = warp_sum(s);
        if (lane == 0) g_w1[wid] = s;
    } else if (wid < NHEADS * 600 + 600) {
        int k = wid - NHEADS * 600;
        float s = 0.f;
        for (int j = lane; j < 200; j += 32)
            s += a_out[j * 600 + k] * a2_o[j];
        s = warp_sum(s);
        if (lane == 0) g_w2[k] = s;
    }
}

// ---------------- prep: B splits (src-first order) + edge arrays -----------
__global__ void prep(const float* __restrict__ a_heads,
                     const float* __restrict__ a_out,
                     const float* __restrict__ W_ent,
                     const int* __restrict__ edge_list,
                     const int* __restrict__ edge_type,
                     const int* __restrict__ nhop) {
    int i = blockIdx.x * blockDim.x + threadIdx.x;
    if (i < 600 * K_PAD) {
        int j = i / K_PAD, k = i % K_PAD;
        float v = 0.f;
        if (k < DIM) {
            if (j < 200) {
                int h = j / NHID, jr = j % NHID;
                v = a_heads[(h * NHID + jr) * 600 + DIM + k];
            } else if (j < 400) {
                int jj = j - 200;
                int h = jj / NHID, jr = jj % NHID;
                v = a_heads[(h * NHID + jr) * 600 + k];
            } else {
                v = W_ent[k * DIM + (j - 400)];
            }
        }
        bf16 hi, lo; split_bf16(v, hi, lo);
        g_BAh[i] = hi; g_BAl[i] = lo;
        if (i < 400 * K_PAD) {
            float v2 = 0.f;
            if (k < DIM) {
                if (j < 200) v2 = a_out[j * 600 + DIM + k];
                else         v2 = a_out[(j - 200) * 600 + k];
            }
            bf16 h2, l2; split_bf16(v2, h2, l2);
            g_B2h[i] = h2; g_B2l[i] = l2;
        }
    }
    if (i < E_ALL) {
        if (i < E_BASE) {
            g_dst[i] = edge_list[i];
            g_src[i] = edge_list[E_BASE + i];
            g_rA[i]  = edge_type[i];
            g_rB[i]  = -1;
        } else {
            int t = i - E_BASE;
            g_dst[i] = nhop[t * 4 + 3];
            g_src[i] = nhop[t * 4 + 0];
            g_rA[i]  = nhop[t * 4 + 1];
            g_rB[i]  = nhop[t * 4 + 2];
        }
    }
}

// ---------------- zero accumulators + mask (vectorized) ----------------
__global__ void zero_all() {
    int stride = gridDim.x * blockDim.x;
    int tid = blockIdx.x * blockDim.x + threadIdx.x;
    const int N1 = N_NODES * 200 / 4;
    const int N2 = N_NODES * DIM / 4;
    float4 z = make_float4(0.f, 0.f, 0.f, 0.f);
    for (int i = tid; i < N1; i += stride) {
        ((float4*)g_acc1)[i] = z;
        if (i < N2) ((float4*)g_acc2)[i] = z;
        if (i < NHEADS * N_NODES) g_rowsum1[i] = 0.f;
        if (i < N_NODES) { g_rowsum2[i] = 0.f; g_mask[i] = 0.f; }
    }
}

__global__ void mask_scatter(const int* __restrict__ batch, int n) {
    int i = blockIdx.x * blockDim.x + threadIdx.x;
    if (i < n) g_mask[batch[i]] = 1.0f;
}

// ---------------- rel kernel A: rp1 + outrel + r1 ----------------
__global__ void relA(const float* __restrict__ rel, const float* __restrict__ a_heads,
                     const float* __restrict__ W_gat) {
    int i = blockIdx.x * blockDim.x + threadIdx.x;
    if (i < NHEADS * N_RELS * NHID) {
        int h = i / (N_RELS * NHID);
        int rem = i % (N_RELS * NHID);
        int r = rem / NHID, j = rem % NHID;
        const float* ar = a_heads + (h * NHID + j) * 600 + 400;
        const float* rr = rel + r * DIM;
        float s = 0.f;
        #pragma unroll 4
        for (int k = 0; k < DIM; k++) s += rr[k] * ar[k];
        g_rp1[r * 200 + h * NHID + j] = s;
    }
    if (i < N_RELS * DIM) {
        int r = i / DIM, j = i % DIM;
        const float* rr = rel + r * DIM;
        float s = 0.f;
        #pragma unroll 4
        for (int k = 0; k < DIM; k++) s += rr[k] * W_gat[k * DIM + j];
        g_outrel[i] = s;
    }
    if (i < NHEADS * N_RELS) {
        int h = i / N_RELS, r = i % N_RELS;
        float s = 0.f;
        for (int k = 0; k < DIM; k++) s += rel[r * DIM + k] * g_w1[h * 600 + 400 + k];
        g_r1[i] = s;
    }
}

// ---------------- rel kernel B: relproj2 + r2 ----------------
__global__ void relB(const float* __restrict__ a_out) {
    int i = blockIdx.x * blockDim.x + threadIdx.x;
    if (i < N_RELS * DIM) {
        int r = i / DIM, j = i % DIM;
        const float* rr = g_outrel + r * DIM;
        const float* ar = a_out + j * 600 + 400;
        float s = 0.f;
        #pragma unroll 4
        for (int k = 0; k < DIM; k++) s += rr[k] * ar[k];
        g_relproj2[i] = s;
    }
    if (i < N_RELS) {
        float s = 0.f;
        for (int k = 0; k < DIM; k++) s += g_outrel[i * DIM + k] * g_w2[400 + k];
        g_r2[i] = s;
    }
}

// ---------------- split-bf16 tensor GEMM, col_base arg for split launch ----
#define GBM 128
#define GBN 128
#define GBK 32
#define SROW 40
#define TILE (GBM * SROW)
#define STAGE_ELEMS (4 * TILE)
#define SMEM_BYTES (2 * STAGE_ELEMS * 2)
#define NKCH (K_PAD / GBK)

extern __shared__ bf16 smem_dyn[];

template <int LAYER>
__global__ __launch_bounds__(256, 2) void gemm_bf16s(int col_base) {
    const bf16 *Ah, *Al, *Bh, *Bl; int M, Nn;
    float *segA, *segB, *segC;
    if (LAYER == 0) {
        Ah = g_xh;  Al = g_xl;  Bh = g_BAh; Bl = g_BAl; M = N_NODES; Nn = 600;
        segA = g_ps1; segB = g_pd1; segC = g_lin;
    } else {
        Ah = g_x1h; Al = g_x1l; Bh = g_B2h; Bl = g_B2l; M = N_NODES; Nn = 400;
        segA = g_ps2; segB = g_pd2; segC = nullptr;
    }

    int tid = threadIdx.x;
    int lane = tid & 31;
    int w = tid >> 5;
    int wm = (w & 3) * 32;
    int wn = (w >> 2) * 64;
    int row0 = blockIdx.y * GBM;
    int col0 = col_base + blockIdx.x * GBN;

    uint32_t ubase = (uint32_t)__cvta_generic_to_shared(smem_dyn);

    int r_ld[2], c8_ld[2];
    #pragma unroll
    for (int i = 0; i < 2; i++) { int idx = tid + 256 * i; r_ld[i] = idx >> 2; c8_ld[i] = (idx & 3) * 8; }
    bool aok[2], bok[2];
    #pragma unroll
    for (int i = 0; i < 2; i++) { aok[i] = (row0 + r_ld[i]) < M; bok[i] = (col0 + r_ld[i]) < Nn; }

    float acc[2][8][4];
    #pragma unroll
    for (int mt = 0; mt < 2; mt++)
        #pragma unroll
        for (int nt = 0; nt < 8; nt++)
            #pragma unroll
            for (int q = 0; q < 4; q++) acc[mt][nt][q] = 0.f;

    auto load_stage = [&](int s, int k0) {
        uint32_t sb = ubase + (uint32_t)(s * STAGE_ELEMS) * 2;
        #pragma unroll
        for (int i = 0; i < 2; i++) {
            int r = r_ld[i], c8 = c8_ld[i];
            uint32_t doff = (uint32_t)(r * SROW + c8) * 2;
            size_t arow = (size_t)(row0 + r) * K_PAD + k0 + c8;
            size_t brow = (size_t)(col0 + r) * K_PAD + k0 + c8;
            cp_async16(sb + 0 * TILE * 2 + doff, Ah + arow, aok[i] ? 16 : 0);
            cp_async16(sb + 1 * TILE * 2 + doff, Al + arow, aok[i] ? 16 : 0);
            cp_async16(sb + 2 * TILE * 2 + doff, Bh + brow, bok[i] ? 16 : 0);
            cp_async16(sb + 3 * TILE * 2 + doff, Bl + brow, bok[i] ? 16 : 0);
        }
        CP_COMMIT();
    };

    load_stage(0, 0);

    int b_row_off = (lane & 7) + ((lane >> 4) & 1) * 8;
    int b_col_off = (lane & 8) ? 8 : 0;

    for (int kt = 0; kt < NKCH; kt++) {
        CP_WAIT(0);
        __syncthreads();
        if (kt + 1 < NKCH) load_stage((kt + 1) & 1, (kt + 1) * GBK);

        uint32_t sb = ubase + (uint32_t)((kt & 1) * STAGE_ELEMS) * 2;
        uint32_t uAh = sb;
        uint32_t uAl = sb + TILE * 2;
        uint32_t uBh = sb + 2 * TILE * 2;
        uint32_t uBl = sb + 3 * TILE * 2;

        #pragma unroll
        for (int k16 = 0; k16 < GBK; k16 += 16) {
            uint32_t ah[2][4], al[2][4];
            #pragma unroll
            for (int mt = 0; mt < 2; mt++) {
                uint32_t off = (uint32_t)((wm + mt * 16 + (lane & 15)) * SROW + k16 + (lane >> 4) * 8) * 2;
                LDSM_X4(ah[mt], uAh + off);
                LDSM_X4(al[mt], uAl + off);
            }
            #pragma unroll
            for (int ntp = 0; ntp < 4; ntp++) {
                uint32_t boff = (uint32_t)((wn + ntp * 16 + b_row_off) * SROW + k16 + b_col_off) * 2;
                uint32_t b4h[4], b4l[4];
                LDSM_X4(b4h, uBh + boff);
                LDSM_X4(b4l, uBl + boff);
                #pragma unroll
                for (int sub = 0; sub < 2; sub++) {
                    int nt = ntp * 2 + sub;
                    uint32_t bh[2] = { b4h[sub * 2], b4h[sub * 2 + 1] };
                    uint32_t bl[2] = { b4l[sub * 2], b4l[sub * 2 + 1] };
                    #pragma unroll
                    for (int mt = 0; mt < 2; mt++) {
                        MMA_BF16(acc[mt][nt], ah[mt], bh);
                        MMA_BF16(acc[mt][nt], ah[mt], bl);
                        MMA_BF16(acc[mt][nt], al[mt], bh);
                    }
                }
            }
        }
    }

    #pragma unroll
    for (int mt = 0; mt < 2; mt++) {
        int r0 = row0 + wm + mt * 16 + (lane >> 2);
        #pragma unroll
        for (int nt = 0; nt < 8; nt++) {
            int c = col0 + wn + nt * 8 + (lane & 3) * 2;
            if (c < Nn) {
                int sg = c / 200;
                int cc = c - sg * 200;
                float* base = (sg == 0) ? segA : ((sg == 1) ? segB : segC);
                if (r0 < M)
                    *(float2*)(base + (size_t)r0 * 200 + cc) = make_float2(acc[mt][nt][0], acc[mt][nt][1]);
                if (r0 + 8 < M)
                    *(float2*)(base + (size_t)(r0 + 8) * 200 + cc) = make_float2(acc[mt][nt][2], acc[mt][nt][3]);
            }
        }
    }
}

// ---------------- edge scatter, layer 1 ----------------
__global__ void edge_scatter1() {
    int gw = (blockIdx.x * blockDim.x + threadIdx.x) >> 5;
    int lane = threadIdx.x & 31;
    if (gw >= E_ALL) return;
    int d = g_dst[gw], s = g_src[gw], ra = g_rA[gw], rb = g_rB[gw];
    float dot0 = g_d1[d] + g_s1[s] + g_r1[ra];
    float dot1 = g_d1[N_NODES + d] + g_s1[N_NODES + s] + g_r1[N_RELS + ra];
    if (rb >= 0) { dot0 += g_r1[rb]; dot1 += g_r1[N_RELS + rb]; }
    float lr0 = dot0 > 0.f ? dot0 : 0.2f * dot0;
    float lr1 = dot1 > 0.f ? dot1 : 0.2f * dot1;
    float ev0 = __expf(-lr0);
    float ev1 = __expf(-lr1);
    if (lane == 0) {
        red_add_f32(&g_rowsum1[d], ev0);
        red_add_f32(&g_rowsum1[N_NODES + d], ev1);
    }
    const float4* ps = (const float4*)(g_ps1 + (size_t)s * 200);
    const float4* rp = (const float4*)(g_rp1 + (size_t)ra * 200);
    const float4* rpb = (rb >= 0) ? (const float4*)(g_rp1 + (size_t)rb * 200) : nullptr;
    float* accrow = g_acc1 + (size_t)d * 200;
    #pragma unroll
    for (int it = 0; it < 2; it++) {
        int q = lane + 32 * it;
        if (q < 50) {
            float ev = (q < 25) ? ev0 : ev1;
            float4 v = ps[q];
            float4 r = rp[q];
            v.x += r.x; v.y += r.y; v.z += r.z; v.w += r.w;
            if (rpb) {
                float4 r2 = rpb[q];
                v.x += r2.x; v.y += r2.y; v.z += r2.z; v.w += r2.w;
            }
            v.x *= ev; v.y *= ev; v.z *= ev; v.w *= ev;
            red_add_v4(accrow + q * 4, v);
        }
    }
}

// ---------------- combine layer-1 -> x1 split + layer-2 node scalars -------
__global__ void combine1() {
    int n = (blockIdx.x * blockDim.x + threadIdx.x) >> 5;
    int lane = threadIdx.x & 31;
    if (n >= N_NODES) return;
    float rs0 = g_rowsum1[n];
    float rs1 = g_rowsum1[N_NODES + n];
    float inv[2];
    inv[0] = (rs0 != 0.f) ? 1.f / rs0 : 0.f;
    inv[1] = (rs1 != 0.f) ? 1.f / rs1 : 0.f;
    bool has[2] = { rs0 != 0.f, rs1 != 0.f };
    const float4* pd = (const float4*)(g_pd1 + (size_t)n * 200);
    const float4* ac = (const float4*)(g_acc1 + (size_t)n * 200);
    uint32_t* xh = (uint32_t*)(g_x1h + (size_t)n * K_PAD);
    uint32_t* xl = (uint32_t*)(g_x1l + (size_t)n * K_PAD);
    const float4* w2a = (const float4*)g_w2;
    const float4* w2b = (const float4*)(g_w2 + 200);
    float d2 = 0.f, s2 = 0.f;
    #pragma unroll
    for (int it = 0; it < 2; it++) {
        int q = lane + 32 * it;
        if (q < 50) {
            int h = (q < 25) ? 0 : 1;
            float4 p = pd[q];
            float4 a = ac[q];
            float iv = inv[h];
            bool hs = has[h];
            float v0 = hs ? p.x + a.x * iv : 0.f;
            float v1 = hs ? p.y + a.y * iv : 0.f;
            float v2 = hs ? p.z + a.z * iv : 0.f;
            float v3 = hs ? p.w + a.w * iv : 0.f;
            v0 = v0 > 0.f ? v0 : (__expf(v0) - 1.f);
            v1 = v1 > 0.f ? v1 : (__expf(v1) - 1.f);
            v2 = v2 > 0.f ? v2 : (__expf(v2) - 1.f);
            v3 = v3 > 0.f ? v3 : (__expf(v3) - 1.f);
            bf16 h0, l0, h1, l1, h2, l2, h3, l3;
            split_bf16(v0, h0, l0); split_bf16(v1, h1, l1);
            split_bf16(v2, h2, l2); split_bf16(v3, h3, l3);
            xh[q * 2]     = pack_bf2(h0, h1);
            xh[q * 2 + 1] = pack_bf2(h2, h3);
            xl[q * 2]     = pack_bf2(l0, l1);
            xl[q * 2 + 1] = pack_bf2(l2, l3);
            float4 wa = w2a[q], wb = w2b[q];
            d2 += v0 * wa.x + v1 * wa.y + v2 * wa.z + v3 * wa.w;
            s2 += v0 * wb.x + v1 * wb.y + v2 * wb.z + v3 * wb.w;
        } else if (q < 56) {
            xh[q * 2] = 0u; xh[q * 2 + 1] = 0u;
            xl[q * 2] = 0u; xl[q * 2 + 1] = 0u;
        }
    }
    d2 = warp_sum(d2); s2 = warp_sum(s2);
    if (lane == 0) { g_d2[n] = d2; g_s2[n] = s2; }
}

// ---------------- edge scatter, layer 2 ----------------
__global__ void edge_scatter2() {
    int gw = (blockIdx.x * blockDim.x + threadIdx.x) >> 5;
    int lane = threadIdx.x & 31;
    if (gw >= E_ALL) return;
    int d = g_dst[gw], s = g_src[gw], ra = g_rA[gw], rb = g_rB[gw];
    float dot = g_d2[d] + g_s2[s] + g_r2[ra];
    if (rb >= 0) dot += g_r2[rb];
    float lr = dot > 0.f ? dot : 0.2f * dot;
    float ev = __expf(-lr);
    if (lane == 0) red_add_f32(&g_rowsum2[d], ev);
    const float4* ps = (const float4*)(g_ps2 + (size_t)s * 200);
    const float4* rp = (const float4*)(g_relproj2 + (size_t)ra * DIM);
    const float4* rpb = (rb >= 0) ? (const float4*)(g_relproj2 + (size_t)rb * DIM) : nullptr;
    float* accrow = g_acc2 + (size_t)d * DIM;
    #pragma unroll
    for (int it = 0; it < 2; it++) {
        int q = lane + 32 * it;
        if (q < 50) {
            float4 v = ps[q];
            float4 r = rp[q];
            v.x += r.x; v.y += r.y; v.z += r.z; v.w += r.w;
            if (rpb) {
                float4 r2 = rpb[q];
                v.x += r2.x; v.y += r2.y; v.z += r2.z; v.w += r2.w;
            }
            v.x *= ev; v.y *= ev; v.z *= ev; v.w *= ev;
            red_add_v4(accrow + q * 4, v);
        }
    }
}

// ---------------- finalize (float4) ----------------
__global__ void finalize(float* __restrict__ out) {
    int n = (blockIdx.x * blockDim.x + threadIdx.x) >> 5;
    int lane = threadIdx.x & 31;
    if (n >= N_NODES) return;
    float rs = g_rowsum2[n];
    bool has = rs != 0.f;
    float iS = has ? 1.f / rs : 0.f;
    float mk = g_mask[n];
    const float4* pd = (const float4*)(g_pd2 + (size_t)n * 200);
    const float4* lin = (const float4*)(g_lin + (size_t)n * 200);
    const float4* acc = (const float4*)(g_acc2 + (size_t)n * DIM);
    float4 vv[2];
    float ss = 0.f;
    #pragma unroll
    for (int it = 0; it < 2; it++) {
        int q = lane + 32 * it;
        float4 val = make_float4(0.f, 0.f, 0.f, 0.f);
        if (q < 50) {
            float4 p = pd[q];
            float4 a = acc[q];
            float4 l = lin[q];
            float h0 = has ? p.x + a.x * iS : 0.f;
            float h1 = has ? p.y + a.y * iS : 0.f;
            float h2 = has ? p.z + a.z * iS : 0.f;
            float h3 = has ? p.w + a.w * iS : 0.f;
            h0 = h0 > 0.f ? h0 : (expf(h0) - 1.f);
            h1 = h1 > 0.f ? h1 : (expf(h1) - 1.f);
            h2 = h2 > 0.f ? h2 : (expf(h2) - 1.f);
            h3 = h3 > 0.f ? h3 : (expf(h3) - 1.f);
            val.x = l.x + mk * h0; val.y = l.y + mk * h1;
            val.z = l.z + mk * h2; val.w = l.w + mk * h3;
            ss += val.x * val.x + val.y * val.y + val.z * val.z + val.w * val.w;
        }
        vv[it] = val;
    }
    ss = warp_sum(ss);
    float sc = 1.f / fmaxf(sqrtf(ss), 1e-12f);
    float4* orow = (float4*)(out + (size_t)n * DIM);
    #pragma unroll
    for (int it = 0; it < 2; it++) {
        int q = lane + 32 * it;
        if (q < 50) {
            float4 v = vv[it];
            v.x *= sc; v.y *= sc; v.z *= sc; v.w *= sc;
            orow[q] = v;
        }
    }
}

__global__ void copy_tail(float* __restrict__ out) {
    int i = blockIdx.x * blockDim.x + threadIdx.x;
    const size_t base = (size_t)N_NODES * DIM;
    if (i < N_RELS * DIM) out[base + i] = g_outrel[i];
    if (i < N_NODES) out[base + N_RELS * DIM + i] = g_mask[i];
}

// ---------------- streams/events (created once at init) ----------------
static cudaStream_t s1, s2, s3, s4;
static cudaEvent_t  e0, eL, e1, e2, e3, e4, eg0, es1, eg2, es2;
namespace {
struct StreamInit {
    StreamInit() {
        cudaStreamCreateWithFlags(&s1, cudaStreamNonBlocking);
        cudaStreamCreateWithFlags(&s2, cudaStreamNonBlocking);
        cudaStreamCreateWithFlags(&s3, cudaStreamNonBlocking);
        cudaStreamCreateWithFlags(&s4, cudaStreamNonBlocking);
        cudaEventCreateWithFlags(&e0,  cudaEventDisableTiming);
        cudaEventCreateWithFlags(&eL,  cudaEventDisableTiming);
        cudaEventCreateWithFlags(&e1,  cudaEventDisableTiming);
        cudaEventCreateWithFlags(&e2,  cudaEventDisableTiming);
        cudaEventCreateWithFlags(&e3,  cudaEventDisableTiming);
        cudaEventCreateWithFlags(&e4,  cudaEventDisableTiming);
        cudaEventCreateWithFlags(&eg0, cudaEventDisableTiming);
        cudaEventCreateWithFlags(&es1, cudaEventDisableTiming);
        cudaEventCreateWithFlags(&eg2, cudaEventDisableTiming);
        cudaEventCreateWithFlags(&es2, cudaEventDisableTiming);
    }
} g_stream_init;
}

// ---------------- launch ----------------
extern "C" void kernel_launch(void* const* d_in, const int* in_sizes, int n_in,
                              void* d_out, int out_size) {
    const float* ent   = (const float*)d_in[0];
    const float* rel   = (const float*)d_in[1];
    const float* W_ent = (const float*)d_in[2];
    const float* W_gat = (const float*)d_in[3];
    const float* a_h   = (const float*)d_in[4];
    const float* a2_h  = (const float*)d_in[5];
    const float* a_o   = (const float*)d_in[6];
    const float* a2_o  = (const float*)d_in[7];
    const int*   batch = (const int*)d_in[8];
    const int*   elist = (const int*)d_in[9];
    const int*   etype = (const int*)d_in[10];
    const int*   nhop  = (const int*)d_in[11];
    float* out = (float*)d_out;
    int n_batch = in_sizes[8];

    const int PREP_N = (600 * K_PAD > E_ALL) ? 600 * K_PAD : E_ALL;
    const int NROW_BLK = (N_NODES + GBM - 1) / GBM;

    cudaFuncSetAttribute(gemm_bf16s<0>, cudaFuncAttributeMaxDynamicSharedMemorySize, SMEM_BYTES);
    cudaFuncSetAttribute(gemm_bf16s<1>, cudaFuncAttributeMaxDynamicSharedMemorySize, SMEM_BYTES);

    // fork
    cudaEventRecord(e0, 0);
    cudaStreamWaitEvent(s1, e0, 0);
    cudaStreamWaitEvent(s2, e0, 0);
    cudaStreamWaitEvent(s3, e0, 0);

    // stream 0 (critical path): l2norm_x immediately — no deps
    l2norm_x<<<(N_NODES * 32 + 255) / 256, 256>>>(ent);
    cudaEventRecord(eL, 0);

    // s1: prep (B tiles + edge arrays)
    prep<<<(PREP_N + 255) / 256, 256, 0, s1>>>(a_h, a_o, W_ent, elist, etype, nhop);
    cudaEventRecord(e1, s1);

    // s3: zero + mask
    zero_all<<<2048, 256, 0, s3>>>();
    mask_scatter<<<(n_batch + 255) / 256, 256, 0, s3>>>(batch, n_batch);
    cudaEventRecord(e3, s3);

    // s2: fold_w -> node_scalars1 (after l2norm) -> relA -> relB -> copy_tail
    fold_w<<<(1800 * 32 + 255) / 256, 256, 0, s2>>>(a_h, a2_h, a_o, a2_o);
    cudaStreamWaitEvent(s2, eL, 0);
    node_scalars1<<<(N_NODES * 32 + 255) / 256, 256, 0, s2>>>();
    relA<<<(NHEADS * N_RELS * NHID + 255) / 256, 256, 0, s2>>>(rel, a_h, W_gat);
    relB<<<(N_RELS * DIM + 255) / 256, 256, 0, s2>>>(a_o);
    cudaEventRecord(e2, s2);
    cudaStreamWaitEvent(s2, e3, 0);
    copy_tail<<<(N_RELS * DIM + 255) / 256, 256, 0, s2>>>(out);
    cudaEventRecord(e4, s2);

    // gemm0 part A: cols 0..255 (covers ps1)
    cudaStreamWaitEvent(0, e1, 0);
    gemm_bf16s<0><<<dim3(2, NROW_BLK), 256, SMEM_BYTES>>>(0);
    cudaEventRecord(eg0, 0);
    // gemm0 part B: cols 256..599 — overlaps scatter1
    gemm_bf16s<0><<<dim3(3, NROW_BLK), 256, SMEM_BYTES>>>(256);

    // s4: edge scatter 1 (needs ps1[eg0], scalars+rels[e2], zeros[e3])
    cudaStreamWaitEvent(s4, eg0, 0);
    cudaStreamWaitEvent(s4, e2, 0);
    cudaStreamWaitEvent(s4, e3, 0);
    edge_scatter1<<<(E_ALL + 7) / 8, 256, 0, s4>>>();
    cudaEventRecord(es1, s4);

    // combine1 (needs pd1 [stream0 partB] + scatter1 [es1])
    cudaStreamWaitEvent(0, es1, 0);
    combine1<<<(N_NODES * 32 + 255) / 256, 256>>>();

    // gemm1 part A: cols 0..255 (covers ps2)
    gemm_bf16s<1><<<dim3(2, NROW_BLK), 256, SMEM_BYTES>>>(0);
    cudaEventRecord(eg2, 0);
    // gemm1 part B: cols 256..399 — overlaps scatter2
    gemm_bf16s<1><<<dim3(2, NROW_BLK), 256, SMEM_BYTES>>>(256);

    // s4: edge scatter 2
    cudaStreamWaitEvent(s4, eg2, 0);
    edge_scatter2<<<(E_ALL + 7) / 8, 256, 0, s4>>>();
    cudaEventRecord(es2, s4);

    // finalize
    cudaStreamWaitEvent(0, es2, 0);
    cudaStreamWaitEvent(0, e3, 0);
    finalize<<<(N_NODES * 32 + 255) / 256, 256>>>(out);

    cudaStreamWaitEvent(0, e4, 0);
}

// round 16
// speedup vs baseline: 1.1240x; 1.1240x over previous
#include <cuda_runtime.h>
#include <cuda_bf16.h>
#include <math.h>
#include <stdint.h>

#define N_NODES 50000
#define DIM     200
#define K_PAD   224
#define N_RELS  500
#define NHID    100
#define NHEADS  2
#define E_BASE  150000
#define E_NHOP  30000
#define E_ALL   180000

typedef __nv_bfloat16 bf16;

// ---------------- scratch (static device globals; no allocs) ----------------
__device__ __align__(16) bf16 g_xh[N_NODES * K_PAD];
__device__ __align__(16) bf16 g_xl[N_NODES * K_PAD];
__device__ __align__(16) bf16 g_x1h[N_NODES * K_PAD];
__device__ __align__(16) bf16 g_x1l[N_NODES * K_PAD];
// BcatA row order: 0-199 SRC (h0,h1), 200-399 DST (h0,h1), 400-599 W_ent^T
__device__ __align__(16) bf16 g_BAh[600 * K_PAD];
__device__ __align__(16) bf16 g_BAl[600 * K_PAD];
// B2 row order: 0-199 SRC, 200-399 DST
__device__ __align__(16) bf16 g_B2h[400 * K_PAD];
__device__ __align__(16) bf16 g_B2l[400 * K_PAD];
__device__ __align__(16) float g_pd1[N_NODES * 200];
__device__ __align__(16) float g_ps1[N_NODES * 200];
__device__ __align__(16) float g_lin[N_NODES * 200];
__device__ __align__(16) float g_pd2[N_NODES * 200];
__device__ __align__(16) float g_ps2[N_NODES * 200];
__device__ __align__(16) float g_rp1[N_RELS * 200];
__device__ __align__(16) float g_relproj2[N_RELS * DIM];
__device__ int   g_dst[E_ALL];
__device__ int   g_src[E_ALL];
__device__ int   g_rA[E_ALL];
__device__ int   g_rB[E_ALL];
__device__ float g_rowsum1[NHEADS * N_NODES];
__device__ __align__(16) float g_acc1[N_NODES * 200];
__device__ float g_outrel[N_RELS * DIM];
__device__ float g_rowsum2[N_NODES];
__device__ __align__(16) float g_acc2[N_NODES * DIM];
__device__ float g_mask[N_NODES];
__device__ float g_w1[NHEADS * 600];
__device__ float g_w2[600];
__device__ float g_d1[NHEADS * N_NODES];
__device__ float g_s1[NHEADS * N_NODES];
__device__ float g_r1[NHEADS * N_RELS];
__device__ float g_d2[N_NODES];
__device__ float g_s2[N_NODES];
__device__ float g_r2[N_RELS];

// ---------------- helpers ----------------
__device__ __forceinline__ float warp_sum(float v) {
    #pragma unroll
    for (int o = 16; o; o >>= 1) v += __shfl_xor_sync(0xFFFFFFFFu, v, o);
    return v;
}

__device__ __forceinline__ void split_bf16(float x, bf16& hi, bf16& lo) {
    hi = __float2bfloat16_rn(x);
    lo = __float2bfloat16_rn(x - __bfloat162float(hi));
}

__device__ __forceinline__ void red_add_v4(float* addr, float4 v) {
    asm volatile("red.global.add.v4.f32 [%0], {%1,%2,%3,%4};"
                 :: "l"(addr), "f"(v.x), "f"(v.y), "f"(v.z), "f"(v.w) : "memory");
}
__device__ __forceinline__ void red_add_f32(float* addr, float v) {
    asm volatile("red.global.add.f32 [%0], %1;" :: "l"(addr), "f"(v) : "memory");
}

#define LDSM_X4(R, addr) asm volatile( \
    "ldmatrix.sync.aligned.m8n8.x4.shared.b16 {%0,%1,%2,%3}, [%4];" \
    : "=r"((R)[0]), "=r"((R)[1]), "=r"((R)[2]), "=r"((R)[3]) : "r"(addr))
#define MMA_BF16(C, A, B) asm volatile( \
    "mma.sync.aligned.m16n8k16.row.col.f32.bf16.bf16.f32 " \
    "{%0,%1,%2,%3}, {%4,%5,%6,%7}, {%8,%9}, {%0,%1,%2,%3};" \
    : "+f"((C)[0]), "+f"((C)[1]), "+f"((C)[2]), "+f"((C)[3]) \
    : "r"((A)[0]), "r"((A)[1]), "r"((A)[2]), "r"((A)[3]), "r"((B)[0]), "r"((B)[1]))

__device__ __forceinline__ void cp_async16(uint32_t dst, const void* src, int szbytes) {
    asm volatile("cp.async.cg.shared.global [%0], [%1], 16, %2;"
                 :: "r"(dst), "l"(src), "r"(szbytes));
}
#define CP_COMMIT() asm volatile("cp.async.commit_group;")
#define CP_WAIT(N)  asm volatile("cp.async.wait_group %0;" :: "n"(N))

__device__ __forceinline__ uint32_t pack_bf2(bf16 a, bf16 b) {
    uint16_t ua = *(uint16_t*)&a, ub = *(uint16_t*)&b;
    return (uint32_t)ua | ((uint32_t)ub << 16);
}

// ---------------- folded attention vectors (warp per output) ----------------
__global__ void fold_w(const float* __restrict__ a_heads, const float* __restrict__ a2_h,
                       const float* __restrict__ a_out,   const float* __restrict__ a2_o) {
    int wid = (blockIdx.x * blockDim.x + threadIdx.x) >> 5;
    int lane = threadIdx.x & 31;
    if (wid < NHEADS * 600) {
        int h = wid / 600, k = wid % 600;
        float s = 0.f;
        for (int j = lane; j < NHID; j += 32)
            s += a_heads[(h * NHID + j) * 600 + k] * a2_h[h * NHID + j];
        s = warp_sum(s);
        if (lane == 0) g_w1[wid] = s;
    } else if (wid < NHEADS * 600 + 600) {
        int k = wid - NHEADS * 600;
        float s = 0.f;
        for (int j = lane; j < 200; j += 32)
            s += a_out[j * 600 + k] * a2_o[j];
        s = warp_sum(s);
        if (lane == 0) g_w2[k] = s;
    }
}

// ---------------- l2norm + bf16 split + node scalars (float4, fused) ------
__global__ void l2norm_conv(const float* __restrict__ in) {
    int n = (blockIdx.x * blockDim.x + threadIdx.x) >> 5;
    int lane = threadIdx.x & 31;
    if (n >= N_NODES) return;
    const float4* r = (const float4*)(in + (size_t)n * DIM);
    float4 v[2];
    float ss = 0.f;
    #pragma unroll
    for (int it = 0; it < 2; it++) {
        int q = lane + 32 * it;
        if (q < 50) {
            float4 x = r[q];
            v[it] = x;
            ss += x.x * x.x + x.y * x.y + x.z * x.z + x.w * x.w;
        } else {
            v[it] = make_float4(0.f, 0.f, 0.f, 0.f);
        }
    }
    ss = warp_sum(ss);
    float sc = 1.f / fmaxf(sqrtf(ss), 1e-12f);
    uint32_t* xh = (uint32_t*)(g_xh + (size_t)n * K_PAD);
    uint32_t* xl = (uint32_t*)(g_xl + (size_t)n * K_PAD);
    const float4* w1a = (const float4*)g_w1;
    const float4* w1b = (const float4*)(g_w1 + 200);
    const float4* w1c = (const float4*)(g_w1 + 600);
    const float4* w1d = (const float4*)(g_w1 + 800);
    float a = 0.f, b = 0.f, c = 0.f, d = 0.f;
    #pragma unroll
    for (int it = 0; it < 2; it++) {
        int q = lane + 32 * it;
        if (q < 50) {
            float4 x = v[it];
            x.x *= sc; x.y *= sc; x.z *= sc; x.w *= sc;
            bf16 h0, l0, h1, l1, h2, l2, h3, l3;
            split_bf16(x.x, h0, l0); split_bf16(x.y, h1, l1);
            split_bf16(x.z, h2, l2); split_bf16(x.w, h3, l3);
            xh[q * 2]     = pack_bf2(h0, h1);
            xh[q * 2 + 1] = pack_bf2(h2, h3);
            xl[q * 2]     = pack_bf2(l0, l1);
            xl[q * 2 + 1] = pack_bf2(l2, l3);
            float4 wa = w1a[q], wb = w1b[q], wc = w1c[q], wd = w1d[q];
            a += x.x * wa.x + x.y * wa.y + x.z * wa.z + x.w * wa.w;
            b += x.x * wb.x + x.y * wb.y + x.z * wb.z + x.w * wb.w;
            c += x.x * wc.x + x.y * wc.y + x.z * wc.z + x.w * wc.w;
            d += x.x * wd.x + x.y * wd.y + x.z * wd.z + x.w * wd.w;
        } else if (q < 56) {
            xh[q * 2] = 0u; xh[q * 2 + 1] = 0u;
            xl[q * 2] = 0u; xl[q * 2 + 1] = 0u;
        }
    }
    a = warp_sum(a); b = warp_sum(b); c = warp_sum(c); d = warp_sum(d);
    if (lane == 0) {
        g_d1[n] = a; g_s1[n] = b;
        g_d1[N_NODES + n] = c; g_s1[N_NODES + n] = d;
    }
}

// ---------------- prep: B splits (src-first order) + edge arrays -----------
__global__ void prep(const float* __restrict__ a_heads,
                     const float* __restrict__ a_out,
                     const float* __restrict__ W_ent,
                     const int* __restrict__ edge_list,
                     const int* __restrict__ edge_type,
                     const int* __restrict__ nhop) {
    int i = blockIdx.x * blockDim.x + threadIdx.x;
    if (i < 600 * K_PAD) {
        int j = i / K_PAD, k = i % K_PAD;
        float v = 0.f;
        if (k < DIM) {
            if (j < 200) {
                int h = j / NHID, jr = j % NHID;
                v = a_heads[(h * NHID + jr) * 600 + DIM + k];
            } else if (j < 400) {
                int jj = j - 200;
                int h = jj / NHID, jr = jj % NHID;
                v = a_heads[(h * NHID + jr) * 600 + k];
            } else {
                v = W_ent[k * DIM + (j - 400)];
            }
        }
        bf16 hi, lo; split_bf16(v, hi, lo);
        g_BAh[i] = hi; g_BAl[i] = lo;
        if (i < 400 * K_PAD) {
            float v2 = 0.f;
            if (k < DIM) {
                if (j < 200) v2 = a_out[j * 600 + DIM + k];
                else         v2 = a_out[(j - 200) * 600 + k];
            }
            bf16 h2, l2; split_bf16(v2, h2, l2);
            g_B2h[i] = h2; g_B2l[i] = l2;
        }
    }
    if (i < E_ALL) {
        if (i < E_BASE) {
            g_dst[i] = edge_list[i];
            g_src[i] = edge_list[E_BASE + i];
            g_rA[i]  = edge_type[i];
            g_rB[i]  = -1;
        } else {
            int t = i - E_BASE;
            g_dst[i] = nhop[t * 4 + 3];
            g_src[i] = nhop[t * 4 + 0];
            g_rA[i]  = nhop[t * 4 + 1];
            g_rB[i]  = nhop[t * 4 + 2];
        }
    }
}

// ---------------- zero accumulators + mask (vectorized) ----------------
__global__ void zero_all() {
    int stride = gridDim.x * blockDim.x;
    int tid = blockIdx.x * blockDim.x + threadIdx.x;
    const int N1 = N_NODES * 200 / 4;
    const int N2 = N_NODES * DIM / 4;
    float4 z = make_float4(0.f, 0.f, 0.f, 0.f);
    for (int i = tid; i < N1; i += stride) {
        ((float4*)g_acc1)[i] = z;
        if (i < N2) ((float4*)g_acc2)[i] = z;
        if (i < NHEADS * N_NODES) g_rowsum1[i] = 0.f;
        if (i < N_NODES) { g_rowsum2[i] = 0.f; g_mask[i] = 0.f; }
    }
}

__global__ void mask_scatter(const int* __restrict__ batch, int n) {
    int i = blockIdx.x * blockDim.x + threadIdx.x;
    if (i < n) g_mask[batch[i]] = 1.0f;
}

// ---------------- rel kernel A: rp1 + outrel + r1 ----------------
__global__ void relA(const float* __restrict__ rel, const float* __restrict__ a_heads,
                     const float* __restrict__ W_gat) {
    int i = blockIdx.x * blockDim.x + threadIdx.x;
    if (i < NHEADS * N_RELS * NHID) {
        int h = i / (N_RELS * NHID);
        int rem = i % (N_RELS * NHID);
        int r = rem / NHID, j = rem % NHID;
        const float* ar = a_heads + (h * NHID + j) * 600 + 400;
        const float* rr = rel + r * DIM;
        float s = 0.f;
        #pragma unroll 4
        for (int k = 0; k < DIM; k++) s += rr[k] * ar[k];
        g_rp1[r * 200 + h * NHID + j] = s;
    }
    if (i < N_RELS * DIM) {
        int r = i / DIM, j = i % DIM;
        const float* rr = rel + r * DIM;
        float s = 0.f;
        #pragma unroll 4
        for (int k = 0; k < DIM; k++) s += rr[k] * W_gat[k * DIM + j];
        g_outrel[i] = s;
    }
    if (i < NHEADS * N_RELS) {
        int h = i / N_RELS, r = i % N_RELS;
        float s = 0.f;
        for (int k = 0; k < DIM; k++) s += rel[r * DIM + k] * g_w1[h * 600 + 400 + k];
        g_r1[i] = s;
    }
}

// ---------------- rel kernel B: relproj2 + r2 ----------------
__global__ void relB(const float* __restrict__ a_out) {
    int i = blockIdx.x * blockDim.x + threadIdx.x;
    if (i < N_RELS * DIM) {
        int r = i / DIM, j = i % DIM;
        const float* rr = g_outrel + r * DIM;
        const float* ar = a_out + j * 600 + 400;
        float s = 0.f;
        #pragma unroll 4
        for (int k = 0; k < DIM; k++) s += rr[k] * ar[k];
        g_relproj2[i] = s;
    }
    if (i < N_RELS) {
        float s = 0.f;
        for (int k = 0; k < DIM; k++) s += g_outrel[i * DIM + k] * g_w2[400 + k];
        g_r2[i] = s;
    }
}

// ---------------- split-bf16 tensor GEMM, col_base arg for split launch ----
#define GBM 128
#define GBN 128
#define GBK 32
#define SROW 40
#define TILE (GBM * SROW)
#define STAGE_ELEMS (4 * TILE)
#define SMEM_BYTES (2 * STAGE_ELEMS * 2)
#define NKCH (K_PAD / GBK)

extern __shared__ bf16 smem_dyn[];

template <int LAYER>
__global__ __launch_bounds__(256, 2) void gemm_bf16s(int col_base) {
    const bf16 *Ah, *Al, *Bh, *Bl; int M, Nn;
    float *segA, *segB, *segC;
    if (LAYER == 0) {
        Ah = g_xh;  Al = g_xl;  Bh = g_BAh; Bl = g_BAl; M = N_NODES; Nn = 600;
        segA = g_ps1; segB = g_pd1; segC = g_lin;
    } else {
        Ah = g_x1h; Al = g_x1l; Bh = g_B2h; Bl = g_B2l; M = N_NODES; Nn = 400;
        segA = g_ps2; segB = g_pd2; segC = nullptr;
    }

    int tid = threadIdx.x;
    int lane = tid & 31;
    int w = tid >> 5;
    int wm = (w & 3) * 32;
    int wn = (w >> 2) * 64;
    int row0 = blockIdx.y * GBM;
    int col0 = col_base + blockIdx.x * GBN;

    uint32_t ubase = (uint32_t)__cvta_generic_to_shared(smem_dyn);

    int r_ld[2], c8_ld[2];
    #pragma unroll
    for (int i = 0; i < 2; i++) { int idx = tid + 256 * i; r_ld[i] = idx >> 2; c8_ld[i] = (idx & 3) * 8; }
    bool aok[2], bok[2];
    #pragma unroll
    for (int i = 0; i < 2; i++) { aok[i] = (row0 + r_ld[i]) < M; bok[i] = (col0 + r_ld[i]) < Nn; }

    float acc[2][8][4];
    #pragma unroll
    for (int mt = 0; mt < 2; mt++)
        #pragma unroll
        for (int nt = 0; nt < 8; nt++)
            #pragma unroll
            for (int q = 0; q < 4; q++) acc[mt][nt][q] = 0.f;

    auto load_stage = [&](int s, int k0) {
        uint32_t sb = ubase + (uint32_t)(s * STAGE_ELEMS) * 2;
        #pragma unroll
        for (int i = 0; i < 2; i++) {
            int r = r_ld[i], c8 = c8_ld[i];
            uint32_t doff = (uint32_t)(r * SROW + c8) * 2;
            size_t arow = (size_t)(row0 + r) * K_PAD + k0 + c8;
            size_t brow = (size_t)(col0 + r) * K_PAD + k0 + c8;
            cp_async16(sb + 0 * TILE * 2 + doff, Ah + arow, aok[i] ? 16 : 0);
            cp_async16(sb + 1 * TILE * 2 + doff, Al + arow, aok[i] ? 16 : 0);
            cp_async16(sb + 2 * TILE * 2 + doff, Bh + brow, bok[i] ? 16 : 0);
            cp_async16(sb + 3 * TILE * 2 + doff, Bl + brow, bok[i] ? 16 : 0);
        }
        CP_COMMIT();
    };

    load_stage(0, 0);

    int b_row_off = (lane & 7) + ((lane >> 4) & 1) * 8;
    int b_col_off = (lane & 8) ? 8 : 0;

    for (int kt = 0; kt < NKCH; kt++) {
        CP_WAIT(0);
        __syncthreads();
        if (kt + 1 < NKCH) load_stage((kt + 1) & 1, (kt + 1) * GBK);

        uint32_t sb = ubase + (uint32_t)((kt & 1) * STAGE_ELEMS) * 2;
        uint32_t uAh = sb;
        uint32_t uAl = sb + TILE * 2;
        uint32_t uBh = sb + 2 * TILE * 2;
        uint32_t uBl = sb + 3 * TILE * 2;

        #pragma unroll
        for (int k16 = 0; k16 < GBK; k16 += 16) {
            uint32_t ah[2][4], al[2][4];
            #pragma unroll
            for (int mt = 0; mt < 2; mt++) {
                uint32_t off = (uint32_t)((wm + mt * 16 + (lane & 15)) * SROW + k16 + (lane >> 4) * 8) * 2;
                LDSM_X4(ah[mt], uAh + off);
                LDSM_X4(al[mt], uAl + off);
            }
            #pragma unroll
            for (int ntp = 0; ntp < 4; ntp++) {
                uint32_t boff = (uint32_t)((wn + ntp * 16 + b_row_off) * SROW + k16 + b_col_off) * 2;
                uint32_t b4h[4], b4l[4];
                LDSM_X4(b4h, uBh + boff);
                LDSM_X4(b4l, uBl + boff);
                #pragma unroll
                for (int sub = 0; sub < 2; sub++) {
                    int nt = ntp * 2 + sub;
                    uint32_t bh[2] = { b4h[sub * 2], b4h[sub * 2 + 1] };
                    uint32_t bl[2] = { b4l[sub * 2], b4l[sub * 2 + 1] };
                    #pragma unroll
                    for (int mt = 0; mt < 2; mt++) {
                        MMA_BF16(acc[mt][nt], ah[mt], bh);
                        MMA_BF16(acc[mt][nt], ah[mt], bl);
                        MMA_BF16(acc[mt][nt], al[mt], bh);
                    }
                }
            }
        }
    }

    #pragma unroll
    for (int mt = 0; mt < 2; mt++) {
        int r0 = row0 + wm + mt * 16 + (lane >> 2);
        #pragma unroll
        for (int nt = 0; nt < 8; nt++) {
            int c = col0 + wn + nt * 8 + (lane & 3) * 2;
            if (c < Nn) {
                int sg = c / 200;
                int cc = c - sg * 200;
                float* base = (sg == 0) ? segA : ((sg == 1) ? segB : segC);
                if (r0 < M)
                    *(float2*)(base + (size_t)r0 * 200 + cc) = make_float2(acc[mt][nt][0], acc[mt][nt][1]);
                if (r0 + 8 < M)
                    *(float2*)(base + (size_t)(r0 + 8) * 200 + cc) = make_float2(acc[mt][nt][2], acc[mt][nt][3]);
            }
        }
    }
}

// ---------------- edge scatter, layer 1 ----------------
__global__ void edge_scatter1() {
    int gw = (blockIdx.x * blockDim.x + threadIdx.x) >> 5;
    int lane = threadIdx.x & 31;
    if (gw >= E_ALL) return;
    int d = g_dst[gw], s = g_src[gw], ra = g_rA[gw], rb = g_rB[gw];
    float dot0 = g_d1[d] + g_s1[s] + g_r1[ra];
    float dot1 = g_d1[N_NODES + d] + g_s1[N_NODES + s] + g_r1[N_RELS + ra];
    if (rb >= 0) { dot0 += g_r1[rb]; dot1 += g_r1[N_RELS + rb]; }
    float lr0 = dot0 > 0.f ? dot0 : 0.2f * dot0;
    float lr1 = dot1 > 0.f ? dot1 : 0.2f * dot1;
    float ev0 = __expf(-lr0);
    float ev1 = __expf(-lr1);
    if (lane == 0) {
        red_add_f32(&g_rowsum1[d], ev0);
        red_add_f32(&g_rowsum1[N_NODES + d], ev1);
    }
    const float4* ps = (const float4*)(g_ps1 + (size_t)s * 200);
    const float4* rp = (const float4*)(g_rp1 + (size_t)ra * 200);
    const float4* rpb = (rb >= 0) ? (const float4*)(g_rp1 + (size_t)rb * 200) : nullptr;
    float* accrow = g_acc1 + (size_t)d * 200;
    #pragma unroll
    for (int it = 0; it < 2; it++) {
        int q = lane + 32 * it;
        if (q < 50) {
            float ev = (q < 25) ? ev0 : ev1;
            float4 v = ps[q];
            float4 r = rp[q];
            v.x += r.x; v.y += r.y; v.z += r.z; v.w += r.w;
            if (rpb) {
                float4 r2 = rpb[q];
                v.x += r2.x; v.y += r2.y; v.z += r2.z; v.w += r2.w;
            }
            v.x *= ev; v.y *= ev; v.z *= ev; v.w *= ev;
            red_add_v4(accrow + q * 4, v);
        }
    }
}

// ---------------- combine layer-1 -> x1 split + layer-2 node scalars -------
__global__ void combine1() {
    int n = (blockIdx.x * blockDim.x + threadIdx.x) >> 5;
    int lane = threadIdx.x & 31;
    if (n >= N_NODES) return;
    float rs0 = g_rowsum1[n];
    float rs1 = g_rowsum1[N_NODES + n];
    float inv[2];
    inv[0] = (rs0 != 0.f) ? 1.f / rs0 : 0.f;
    inv[1] = (rs1 != 0.f) ? 1.f / rs1 : 0.f;
    bool has[2] = { rs0 != 0.f, rs1 != 0.f };
    const float4* pd = (const float4*)(g_pd1 + (size_t)n * 200);
    const float4* ac = (const float4*)(g_acc1 + (size_t)n * 200);
    uint32_t* xh = (uint32_t*)(g_x1h + (size_t)n * K_PAD);
    uint32_t* xl = (uint32_t*)(g_x1l + (size_t)n * K_PAD);
    const float4* w2a = (const float4*)g_w2;
    const float4* w2b = (const float4*)(g_w2 + 200);
    float d2 = 0.f, s2 = 0.f;
    #pragma unroll
    for (int it = 0; it < 2; it++) {
        int q = lane + 32 * it;
        if (q < 50) {
            int h = (q < 25) ? 0 : 1;
            float4 p = pd[q];
            float4 a = ac[q];
            float iv = inv[h];
            bool hs = has[h];
            float v0 = hs ? p.x + a.x * iv : 0.f;
            float v1 = hs ? p.y + a.y * iv : 0.f;
            float v2 = hs ? p.z + a.z * iv : 0.f;
            float v3 = hs ? p.w + a.w * iv : 0.f;
            v0 = v0 > 0.f ? v0 : (__expf(v0) - 1.f);
            v1 = v1 > 0.f ? v1 : (__expf(v1) - 1.f);
            v2 = v2 > 0.f ? v2 : (__expf(v2) - 1.f);
            v3 = v3 > 0.f ? v3 : (__expf(v3) - 1.f);
            bf16 h0, l0, h1, l1, h2, l2, h3, l3;
            split_bf16(v0, h0, l0); split_bf16(v1, h1, l1);
            split_bf16(v2, h2, l2); split_bf16(v3, h3, l3);
            xh[q * 2]     = pack_bf2(h0, h1);
            xh[q * 2 + 1] = pack_bf2(h2, h3);
            xl[q * 2]     = pack_bf2(l0, l1);
            xl[q * 2 + 1] = pack_bf2(l2, l3);
            float4 wa = w2a[q], wb = w2b[q];
            d2 += v0 * wa.x + v1 * wa.y + v2 * wa.z + v3 * wa.w;
            s2 += v0 * wb.x + v1 * wb.y + v2 * wb.z + v3 * wb.w;
        } else if (q < 56) {
            xh[q * 2] = 0u; xh[q * 2 + 1] = 0u;
            xl[q * 2] = 0u; xl[q * 2 + 1] = 0u;
        }
    }
    d2 = warp_sum(d2); s2 = warp_sum(s2);
    if (lane == 0) { g_d2[n] = d2; g_s2[n] = s2; }
}

// ---------------- edge scatter, layer 2 ----------------
__global__ void edge_scatter2() {
    int gw = (blockIdx.x * blockDim.x + threadIdx.x) >> 5;
    int lane = threadIdx.x & 31;
    if (gw >= E_ALL) return;
    int d = g_dst[gw], s = g_src[gw], ra = g_rA[gw], rb = g_rB[gw];
    float dot = g_d2[d] + g_s2[s] + g_r2[ra];
    if (rb >= 0) dot += g_r2[rb];
    float lr = dot > 0.f ? dot : 0.2f * dot;
    float ev = __expf(-lr);
    if (lane == 0) red_add_f32(&g_rowsum2[d], ev);
    const float4* ps = (const float4*)(g_ps2 + (size_t)s * 200);
    const float4* rp = (const float4*)(g_relproj2 + (size_t)ra * DIM);
    const float4* rpb = (rb >= 0) ? (const float4*)(g_relproj2 + (size_t)rb * DIM) : nullptr;
    float* accrow = g_acc2 + (size_t)d * DIM;
    #pragma unroll
    for (int it = 0; it < 2; it++) {
        int q = lane + 32 * it;
        if (q < 50) {
            float4 v = ps[q];
            float4 r = rp[q];
            v.x += r.x; v.y += r.y; v.z += r.z; v.w += r.w;
            if (rpb) {
                float4 r2 = rpb[q];
                v.x += r2.x; v.y += r2.y; v.z += r2.z; v.w += r2.w;
            }
            v.x *= ev; v.y *= ev; v.z *= ev; v.w *= ev;
            red_add_v4(accrow + q * 4, v);
        }
    }
}

// ---------------- finalize (float4) ----------------
__global__ void finalize(float* __restrict__ out) {
    int n = (blockIdx.x * blockDim.x + threadIdx.x) >> 5;
    int lane = threadIdx.x & 31;
    if (n >= N_NODES) return;
    float rs = g_rowsum2[n];
    bool has = rs != 0.f;
    float iS = has ? 1.f / rs : 0.f;
    float mk = g_mask[n];
    const float4* pd = (const float4*)(g_pd2 + (size_t)n * 200);
    const float4* lin = (const float4*)(g_lin + (size_t)n * 200);
    const float4* acc = (const float4*)(g_acc2 + (size_t)n * DIM);
    float4 vv[2];
    float ss = 0.f;
    #pragma unroll
    for (int it = 0; it < 2; it++) {
        int q = lane + 32 * it;
        float4 val = make_float4(0.f, 0.f, 0.f, 0.f);
        if (q < 50) {
            float4 p = pd[q];
            float4 a = acc[q];
            float4 l = lin[q];
            float h0 = has ? p.x + a.x * iS : 0.f;
            float h1 = has ? p.y + a.y * iS : 0.f;
            float h2 = has ? p.z + a.z * iS : 0.f;
            float h3 = has ? p.w + a.w * iS : 0.f;
            h0 = h0 > 0.f ? h0 : (expf(h0) - 1.f);
            h1 = h1 > 0.f ? h1 : (expf(h1) - 1.f);
            h2 = h2 > 0.f ? h2 : (expf(h2) - 1.f);
            h3 = h3 > 0.f ? h3 : (expf(h3) - 1.f);
            val.x = l.x + mk * h0; val.y = l.y + mk * h1;
            val.z = l.z + mk * h2; val.w = l.w + mk * h3;
            ss += val.x * val.x + val.y * val.y + val.z * val.z + val.w * val.w;
        }
        vv[it] = val;
    }
    ss = warp_sum(ss);
    float sc = 1.f / fmaxf(sqrtf(ss), 1e-12f);
    float4* orow = (float4*)(out + (size_t)n * DIM);
    #pragma unroll
    for (int it = 0; it < 2; it++) {
        int q = lane + 32 * it;
        if (q < 50) {
            float4 v = vv[it];
            v.x *= sc; v.y *= sc; v.z *= sc; v.w *= sc;
            orow[q] = v;
        }
    }
}

__global__ void copy_tail(float* __restrict__ out) {
    int i = blockIdx.x * blockDim.x + threadIdx.x;
    const size_t base = (size_t)N_NODES * DIM;
    if (i < N_RELS * DIM) out[base + i] = g_outrel[i];
    if (i < N_NODES) out[base + N_RELS * DIM + i] = g_mask[i];
}

// ---------------- streams/events (created once at init) ----------------
static cudaStream_t s1, s2, s3, s4;
static cudaEvent_t  e0, eF, e1, e2, e3, e4, eg0, es1, eg2, es2;
namespace {
struct StreamInit {
    StreamInit() {
        cudaStreamCreateWithFlags(&s1, cudaStreamNonBlocking);
        cudaStreamCreateWithFlags(&s2, cudaStreamNonBlocking);
        cudaStreamCreateWithFlags(&s3, cudaStreamNonBlocking);
        cudaStreamCreateWithFlags(&s4, cudaStreamNonBlocking);
        cudaEventCreateWithFlags(&e0,  cudaEventDisableTiming);
        cudaEventCreateWithFlags(&eF,  cudaEventDisableTiming);
        cudaEventCreateWithFlags(&e1,  cudaEventDisableTiming);
        cudaEventCreateWithFlags(&e2,  cudaEventDisableTiming);
        cudaEventCreateWithFlags(&e3,  cudaEventDisableTiming);
        cudaEventCreateWithFlags(&e4,  cudaEventDisableTiming);
        cudaEventCreateWithFlags(&eg0, cudaEventDisableTiming);
        cudaEventCreateWithFlags(&es1, cudaEventDisableTiming);
        cudaEventCreateWithFlags(&eg2, cudaEventDisableTiming);
        cudaEventCreateWithFlags(&es2, cudaEventDisableTiming);
    }
} g_stream_init;
}

// ---------------- launch (R14 schedule) ----------------
extern "C" void kernel_launch(void* const* d_in, const int* in_sizes, int n_in,
                              void* d_out, int out_size) {
    const float* ent   = (const float*)d_in[0];
    const float* rel   = (const float*)d_in[1];
    const float* W_ent = (const float*)d_in[2];
    const float* W_gat = (const float*)d_in[3];
    const float* a_h   = (const float*)d_in[4];
    const float* a2_h  = (const float*)d_in[5];
    const float* a_o   = (const float*)d_in[6];
    const float* a2_o  = (const float*)d_in[7];
    const int*   batch = (const int*)d_in[8];
    const int*   elist = (const int*)d_in[9];
    const int*   etype = (const int*)d_in[10];
    const int*   nhop  = (const int*)d_in[11];
    float* out = (float*)d_out;
    int n_batch = in_sizes[8];

    const int PREP_N = (600 * K_PAD > E_ALL) ? 600 * K_PAD : E_ALL;
    const int NROW_BLK = (N_NODES + GBM - 1) / GBM;

    cudaFuncSetAttribute(gemm_bf16s<0>, cudaFuncAttributeMaxDynamicSharedMemorySize, SMEM_BYTES);
    cudaFuncSetAttribute(gemm_bf16s<1>, cudaFuncAttributeMaxDynamicSharedMemorySize, SMEM_BYTES);

    // fork
    cudaEventRecord(e0, 0);
    cudaStreamWaitEvent(s1, e0, 0);
    cudaStreamWaitEvent(s3, e0, 0);

    // s1: prep (B tiles + edge arrays)
    prep<<<(PREP_N + 255) / 256, 256, 0, s1>>>(a_h, a_o, W_ent, elist, etype, nhop);
    cudaEventRecord(e1, s1);

    // s3: zero + mask
    zero_all<<<2048, 256, 0, s3>>>();
    mask_scatter<<<(n_batch + 255) / 256, 256, 0, s3>>>(batch, n_batch);
    cudaEventRecord(e3, s3);

    // stream 0 (critical path): fold_w -> l2norm_conv (fused scalars)
    fold_w<<<(1800 * 32 + 255) / 256, 256>>>(a_h, a2_h, a_o, a2_o);
    cudaEventRecord(eF, 0);
    cudaStreamWaitEvent(s2, eF, 0);

    // s2: relA -> relB -> copy_tail (after mask)
    relA<<<(NHEADS * N_RELS * NHID + 255) / 256, 256, 0, s2>>>(rel, a_h, W_gat);
    relB<<<(N_RELS * DIM + 255) / 256, 256, 0, s2>>>(a_o);
    cudaEventRecord(e2, s2);
    cudaStreamWaitEvent(s2, e3, 0);
    copy_tail<<<(N_RELS * DIM + 255) / 256, 256, 0, s2>>>(out);
    cudaEventRecord(e4, s2);

    l2norm_conv<<<(N_NODES * 32 + 255) / 256, 256>>>(ent);

    // gemm0 part A: cols 0..255 (covers ps1)
    cudaStreamWaitEvent(0, e1, 0);
    gemm_bf16s<0><<<dim3(2, NROW_BLK), 256, SMEM_BYTES>>>(0);
    cudaEventRecord(eg0, 0);
    // gemm0 part B: cols 256..599 — overlaps scatter1
    gemm_bf16s<0><<<dim3(3, NROW_BLK), 256, SMEM_BYTES>>>(256);

    // s4: edge scatter 1 (needs ps1[eg0], rels[e2], zeros[e3])
    cudaStreamWaitEvent(s4, eg0, 0);
    cudaStreamWaitEvent(s4, e2, 0);
    cudaStreamWaitEvent(s4, e3, 0);
    edge_scatter1<<<(E_ALL + 7) / 8, 256, 0, s4>>>();
    cudaEventRecord(es1, s4);

    // combine1 (needs pd1 [stream0 partB] + scatter1 [es1])
    cudaStreamWaitEvent(0, es1, 0);
    combine1<<<(N_NODES * 32 + 255) / 256, 256>>>();

    // gemm1 part A: cols 0..255 (covers ps2)
    gemm_bf16s<1><<<dim3(2, NROW_BLK), 256, SMEM_BYTES>>>(0);
    cudaEventRecord(eg2, 0);
    // gemm1 part B: cols 256..399 — overlaps scatter2
    gemm_bf16s<1><<<dim3(2, NROW_BLK), 256, SMEM_BYTES>>>(256);

    // s4: edge scatter 2
    cudaStreamWaitEvent(s4, eg2, 0);
    edge_scatter2<<<(E_ALL + 7) / 8, 256, 0, s4>>>();
    cudaEventRecord(es2, s4);

    // finalize
    cudaStreamWaitEvent(0, es2, 0);
    cudaStreamWaitEvent(0, e3, 0);
    finalize<<<(N_NODES * 32 + 255) / 256, 256>>>(out);

    cudaStreamWaitEvent(0, e4, 0);
}